// round 14
// baseline (speedup 1.0000x reference)
#include <cuda_runtime.h>
#include <cuda_fp16.h>
#include <math.h>
#include <stdint.h>

#define BB 32
#define SS 2048
#define KK 512
#define VV 512
#define HH 256
#define MT (SS*BB)      // 65536 rows (row = s*BB + b)
#define SCH 32          // s-chunks for weighted-sum split
#define SPER (SS/SCH)   // 64

// scratch (static device arrays — no allocation allowed)
__device__ float g_hq2[BB*HH];            // q@Wq + bq + bk, [b][h]
__device__ float g_logit[MT];             // logit[s*BB + b]
__device__ float g_partial[SCH*BB*VV];    // split-S partial weighted sums

__device__ __forceinline__ uint32_t f2h2(float lo, float hi) {
    __half2 h = __floats2half2_rn(lo, hi);
    return *(uint32_t*)&h;
}

#define MMA_F16(d, a, b)                                                        \
    asm volatile("mma.sync.aligned.m16n8k16.row.col.f32.f16.f16.f32 "           \
                 "{%0,%1,%2,%3}, {%4,%5,%6,%7}, {%8,%9}, {%0,%1,%2,%3};"        \
                 : "+f"(d[0]), "+f"(d[1]), "+f"(d[2]), "+f"(d[3])               \
                 : "r"(a[0]), "r"(a[1]), "r"(a[2]), "r"(a[3]),                  \
                   "r"(b[0]), "r"(b[1]))

// ---------------------------------------------------------------------------
// Kernel 1: hq2[b][h] = q[b]·Wq[h] + bq[h] + bk[h]
// ---------------------------------------------------------------------------
__global__ void hq_kernel(const float* __restrict__ q, const float* __restrict__ Wq,
                          const float* __restrict__ bq, const float* __restrict__ bk) {
    int b = blockIdx.x;
    int h = threadIdx.x;  // 256 threads, one per h
    __shared__ float qs[KK];
    for (int i = threadIdx.x; i < KK; i += blockDim.x) qs[i] = q[b*KK + i];
    __syncthreads();
    const float* w = Wq + (size_t)h * KK;
    float acc = 0.f;
    #pragma unroll 8
    for (int kk = 0; kk < KK; kk++) acc += qs[kk] * w[kk];
    g_hq2[b*HH + h] = acc + bq[h] + bk[h];
}

// ---------------------------------------------------------------------------
// Kernel 2: fp16 tensor-core GEMM (fp32 accum) + tanh + Wo reduce -> logit
// A (k rows) and B (Wk rows) staged as half2 in smem, K-major, 16 halves
// (= 8 b32) per row padded to stride 12 b32 -> all fragment LDS conflict-free:
//   bank(row,t) = (row*12 + t) mod 32 ; g*12 mod 32 = {0,12,24,4,16,28,8,20}
// Double-buffered, register prefetch, one __syncthreads per BK=16 tile.
// CTA 512 thr (warp grid 4x4), tile 128x256. MMA = m16n8k16 (half the
// instruction count of the tf32 m16n8k8 version at equal mantissa width).
// ---------------------------------------------------------------------------
#define ROWSTR 12                     // b32 stride per 16-half row
#define NK_TILES (KK/16)
#define LOGIT_SMEM ((2*128*ROWSTR + 2*256*ROWSTR)*4 + HH*4 + 128*4*4)

__global__ __launch_bounds__(512, 1) void logit_kernel(
    const float* __restrict__ kmat, const float* __restrict__ Wk,
    const float* __restrict__ Wo,   const float* __restrict__ bo) {
    extern __shared__ char smem_raw[];
    uint32_t* AsBuf[2];
    uint32_t* BsBuf[2];
    AsBuf[0] = (uint32_t*)smem_raw;                 // 128 rows x 12
    AsBuf[1] = AsBuf[0] + 128*ROWSTR;
    BsBuf[0] = AsBuf[1] + 128*ROWSTR;               // 256 rows x 12
    BsBuf[1] = BsBuf[0] + 256*ROWSTR;
    float* wos = (float*)(BsBuf[1] + 256*ROWSTR);   // [HH]
    float* red = wos + HH;                           // [128][4]

    const int tid  = threadIdx.x;
    const int lane = tid & 31;
    const int warp = tid >> 5;
    const int wm   = warp >> 2;            // 0..3 (M)
    const int wn   = warp & 3;             // 0..3 (N)
    const int g    = lane >> 2;            // groupID
    const int t    = lane & 3;             // thread-in-group
    const int base = blockIdx.x * 128;

    if (tid < HH) wos[tid] = Wo[tid];

    // staging indices
    const int arow = tid >> 2;             // 0..127 (A row)
    const int aseg = tid & 3;              // 4-half segment
    const int bn   = tid >> 1;             // 0..255 (B row = h)
    const int bseg = tid & 1;              // 8-half segment

    float acc[2][8][4];
    #pragma unroll
    for (int mt = 0; mt < 2; mt++)
        #pragma unroll
        for (int nt = 0; nt < 8; nt++)
            #pragma unroll
            for (int c = 0; c < 4; c++) acc[mt][nt][c] = 0.f;

    const float* apt = kmat + (size_t)(base + arow)*KK + aseg*4;
    const float* bpt = Wk + (size_t)bn*KK + bseg*8;

    // ---- prologue: tile 0 -> regs -> smem buf 0 ----
    float4 av  = *(const float4*)(apt);
    float4 bv0 = *(const float4*)(bpt);
    float4 bv1 = *(const float4*)(bpt + 4);
    {
        uint32_t* As = AsBuf[0];
        uint32_t* Bs = BsBuf[0];
        uint2 ah;
        ah.x = f2h2(av.x, av.y);  ah.y = f2h2(av.z, av.w);
        *(uint2*)&As[arow*ROWSTR + aseg*2] = ah;
        uint4 bh;
        bh.x = f2h2(bv0.x, bv0.y); bh.y = f2h2(bv0.z, bv0.w);
        bh.z = f2h2(bv1.x, bv1.y); bh.w = f2h2(bv1.z, bv1.w);
        *(uint4*)&Bs[bn*ROWSTR + bseg*4] = bh;
    }
    __syncthreads();

    for (int it = 0; it < NK_TILES; it++) {
        // issue gmem loads for tile it+1 BEFORE compute (latency hidden by MMAs)
        if (it + 1 < NK_TILES) {
            int kn = (it + 1) * 16;
            av  = *(const float4*)(apt + kn);
            bv0 = *(const float4*)(bpt + kn);
            bv1 = *(const float4*)(bpt + kn + 4);
        }

        const uint32_t* As = AsBuf[it & 1];
        const uint32_t* Bs = BsBuf[it & 1];
        // fragments (m16n8k16): a0=(g,2t:2t+1) a1=(g+8,·) a2=(g,2t+8:9) a3=(g+8,·)
        uint32_t afr[2][4];
        #pragma unroll
        for (int mt = 0; mt < 2; mt++) {
            int r = wm*32 + mt*16;
            afr[mt][0] = As[(r + g    )*ROWSTR + t    ];
            afr[mt][1] = As[(r + g + 8)*ROWSTR + t    ];
            afr[mt][2] = As[(r + g    )*ROWSTR + t + 4];
            afr[mt][3] = As[(r + g + 8)*ROWSTR + t + 4];
        }
        uint32_t bfr[8][2];
        #pragma unroll
        for (int nt = 0; nt < 8; nt++) {
            int n = wn*64 + nt*8 + g;
            bfr[nt][0] = Bs[n*ROWSTR + t    ];
            bfr[nt][1] = Bs[n*ROWSTR + t + 4];
        }
        #pragma unroll
        for (int mt = 0; mt < 2; mt++)
            #pragma unroll
            for (int nt = 0; nt < 8; nt++)
                MMA_F16(acc[mt][nt], afr[mt], bfr[nt]);

        // store prefetched tile into the other buffer
        if (it + 1 < NK_TILES) {
            uint32_t* Asn = AsBuf[(it + 1) & 1];
            uint32_t* Bsn = BsBuf[(it + 1) & 1];
            uint2 ah;
            ah.x = f2h2(av.x, av.y);  ah.y = f2h2(av.z, av.w);
            *(uint2*)&Asn[arow*ROWSTR + aseg*2] = ah;
            uint4 bh;
            bh.x = f2h2(bv0.x, bv0.y); bh.y = f2h2(bv0.z, bv0.w);
            bh.z = f2h2(bv1.x, bv1.y); bh.w = f2h2(bv1.z, bv1.w);
            *(uint4*)&Bsn[bn*ROWSTR + bseg*4] = bh;
        }
        __syncthreads();
    }

    // epilogue: tanh + Wo-weighted reduce across H
    // C mapping: c0 -> (row g, col 2t), c1 -> (g, 2t+1), c2/c3 -> row g+8
    float bo0 = bo[0];
    #pragma unroll
    for (int mt = 0; mt < 2; mt++) {
        #pragma unroll
        for (int rr = 0; rr < 2; rr++) {
            int row_local = wm*32 + mt*16 + rr*8 + g;
            int b = (base + row_local) & (BB - 1);
            const float* hqb = g_hq2 + b*HH;
            float part = 0.f;
            #pragma unroll
            for (int nt = 0; nt < 8; nt++) {
                int h0 = wn*64 + nt*8 + t*2;
                float x0 = acc[mt][nt][rr*2+0] + __ldg(hqb + h0);
                float x1 = acc[mt][nt][rr*2+1] + __ldg(hqb + h0 + 1);
                part += wos[h0] * tanhf(x0) + wos[h0+1] * tanhf(x1);
            }
            part += __shfl_xor_sync(0xffffffffu, part, 1);
            part += __shfl_xor_sync(0xffffffffu, part, 2);
            if (t == 0) red[row_local*4 + wn] = part;
        }
    }
    __syncthreads();
    if (tid < 128)
        g_logit[base + tid] = red[tid*4+0] + red[tid*4+1] + red[tid*4+2] + red[tid*4+3] + bo0;
}

// ---------------------------------------------------------------------------
// Kernel 3: softmax per batch over S; writes final p[b*S+s] into the output.
// ---------------------------------------------------------------------------
__global__ void softmax_kernel(float* __restrict__ p) {
    int b = blockIdx.x, t = threadIdx.x;   // 256 threads
    __shared__ float red[256];
    float m = -3.4e38f;
    for (int s = t; s < SS; s += 256) m = fmaxf(m, g_logit[s*BB + b]);
    red[t] = m; __syncthreads();
    for (int off = 128; off; off >>= 1) {
        if (t < off) red[t] = fmaxf(red[t], red[t + off]);
        __syncthreads();
    }
    m = red[0]; __syncthreads();

    float sum = 0.f;
    for (int s = t; s < SS; s += 256) {
        float e = expf(g_logit[s*BB + b] - m);
        p[b*SS + s] = e;
        sum += e;
    }
    red[t] = sum; __syncthreads();
    for (int off = 128; off; off >>= 1) {
        if (t < off) red[t] += red[t + off];
        __syncthreads();
    }
    float rinv = 1.f / red[0];
    for (int s = t; s < SS; s += 256) p[b*SS + s] *= rinv;
}

// ---------------------------------------------------------------------------
// Kernel 4: partial weighted sum over an s-chunk (float4, smem-staged p):
//   g_partial[sc][b][vc] = sum_{s in chunk} p[b][s] * v[s][b][vc]
// ---------------------------------------------------------------------------
__global__ void wsum_kernel(const float* __restrict__ v, const float* __restrict__ p) {
    int b  = blockIdx.x;
    int sc = blockIdx.y;
    int vc4 = threadIdx.x;   // 128 threads, one float4 each (covers V=512)
    __shared__ float ps[SPER];
    if (threadIdx.x < SPER) ps[threadIdx.x] = p[b*SS + sc*SPER + threadIdx.x];
    __syncthreads();

    const float4* vp = (const float4*)(v + ((size_t)(sc*SPER)*BB + b) * VV) + vc4;
    const size_t stride4 = (size_t)BB * VV / 4;  // float4 stride over s
    float4 acc = make_float4(0.f, 0.f, 0.f, 0.f);
    #pragma unroll 8
    for (int s = 0; s < SPER; s++) {
        float  w = ps[s];
        float4 tv = vp[(size_t)s * stride4];
        acc.x += w * tv.x; acc.y += w * tv.y;
        acc.z += w * tv.z; acc.w += w * tv.w;
    }
    ((float4*)(g_partial + ((size_t)(sc*BB + b)) * VV))[vc4] = acc;
}

// ---------------------------------------------------------------------------
// Kernel 5: reduce split-S partials -> out[b*V + vc]  (deterministic)
// ---------------------------------------------------------------------------
__global__ void reduce_kernel(float* __restrict__ out) {
    int idx = blockIdx.x * 256 + threadIdx.x;  // 16384 total
    float acc = 0.f;
    #pragma unroll
    for (int c = 0; c < SCH; c++) acc += g_partial[c*BB*VV + idx];
    out[idx] = acc;
}

// ---------------------------------------------------------------------------
extern "C" void kernel_launch(void* const* d_in, const int* in_sizes, int n_in,
                              void* d_out, int out_size) {
    const float* q  = (const float*)d_in[0];
    const float* k  = (const float*)d_in[1];
    const float* v  = (const float*)d_in[2];
    const float* Wk = (const float*)d_in[3];
    const float* bk = (const float*)d_in[4];
    const float* Wq = (const float*)d_in[5];
    const float* bq = (const float*)d_in[6];
    const float* Wo = (const float*)d_in[7];
    const float* bo = (const float*)d_in[8];

    float* out = (float*)d_out;          // [1, B, V] -> B*V floats
    float* p   = out + BB*VV;            // [B, S]    -> B*S floats

    static int smem_set = 0;
    if (!smem_set) {
        cudaFuncSetAttribute(logit_kernel,
                             cudaFuncAttributeMaxDynamicSharedMemorySize, LOGIT_SMEM);
        smem_set = 1;
    }

    hq_kernel<<<BB, HH>>>(q, Wq, bq, bk);
    logit_kernel<<<MT/128, 512, LOGIT_SMEM>>>(k, Wk, Wo, bo);
    softmax_kernel<<<BB, 256>>>(p);
    dim3 g4(BB, SCH);
    wsum_kernel<<<g4, 128>>>(v, p);
    reduce_kernel<<<BB*VV/256, 256>>>(out);
}

// round 15
// speedup vs baseline: 1.0129x; 1.0129x over previous
#include <cuda_runtime.h>
#include <math.h>
#include <stdint.h>

#define BB 32
#define SS 2048
#define KK 512
#define VV 512
#define HH 256
#define MT (SS*BB)      // 65536 rows (row = s*BB + b)
#define SCH 64          // s-chunks for weighted-sum split
#define SPER (SS/SCH)   // 32

// scratch (static device arrays — no allocation allowed)
__device__ float g_hq2[BB*HH];            // q@Wq + bq + bk, [b][h]
__device__ float g_logit[MT];             // logit[s*BB + b]
__device__ float g_partial[SCH*BB*VV];    // split-S partial weighted sums (4MB)

__device__ __forceinline__ uint32_t f2tf32(float f) {
    uint32_t r;
    asm("cvt.rna.tf32.f32 %0, %1;" : "=r"(r) : "f"(f));
    return r;
}

#define MMA_TF32(d, a, b)                                                       \
    asm volatile("mma.sync.aligned.m16n8k8.row.col.f32.tf32.tf32.f32 "          \
                 "{%0,%1,%2,%3}, {%4,%5,%6,%7}, {%8,%9}, {%0,%1,%2,%3};"        \
                 : "+f"((d)[0]), "+f"((d)[1]), "+f"((d)[2]), "+f"((d)[3])       \
                 : "r"((a)[0]), "r"((a)[1]), "r"((a)[2]), "r"((a)[3]),          \
                   "r"((b)[0]), "r"((b)[1]))

// ---------------------------------------------------------------------------
// Kernel 1: hq2[b][h] = q[b]·Wq[h] + bq[h] + bk[h]   (grid BB x 8, 256 thr)
// ---------------------------------------------------------------------------
__global__ void hq_kernel(const float* __restrict__ q, const float* __restrict__ Wq,
                          const float* __restrict__ bq, const float* __restrict__ bk) {
    int b = blockIdx.x;
    int h = blockIdx.y * 32 + (threadIdx.x >> 3);
    int seg = threadIdx.x & 7;             // 64-elem segment of K
    const float4* qp = (const float4*)(q + b*KK + seg*64);
    const float4* wp = (const float4*)(Wq + (size_t)h*KK + seg*64);
    float acc = 0.f;
    #pragma unroll
    for (int i = 0; i < 16; i++) {
        float4 qv = qp[i], wv = wp[i];
        acc += qv.x*wv.x + qv.y*wv.y + qv.z*wv.z + qv.w*wv.w;
    }
    acc += __shfl_xor_sync(0xffffffffu, acc, 1);
    acc += __shfl_xor_sync(0xffffffffu, acc, 2);
    acc += __shfl_xor_sync(0xffffffffu, acc, 4);
    if (seg == 0) g_hq2[b*HH + h] = acc + bq[h] + bk[h];
}

// ---------------------------------------------------------------------------
// Kernel 2: HYBRID tensor+FFMA GEMM + tanh + Wo reduce -> logit[row]
//   warps 0..11 (tensor, tf32 mma): cols 0..191, warp grid 4(M) x 3(N)
//   warps 12..15 (FFMA, fp32):      cols 192..255, each warp 32 rows x 64 cols
// CTA 512 thr, tile M=128 x N=256(H), BK=16, double-buffered, reg prefetch.
// ---------------------------------------------------------------------------
#define AS_STR 20      // A row stride (b32) : conflict-free both paths
#define BT_STR 200     // tensor B row stride (200 mod 32 == 8, as R5's 264)
#define BF_STR 72      // FFMA  B row stride
#define NK_TILES (KK/16)
#define LOGIT_SMEM ((2*128*AS_STR + 2*16*BT_STR + 2*16*BF_STR)*4 + HH*4 + 128*4*4)

__global__ __launch_bounds__(512, 1) void logit_kernel(
    const float* __restrict__ kmat, const float* __restrict__ Wk,
    const float* __restrict__ Wo,   const float* __restrict__ bo) {
    extern __shared__ char smem_raw[];
    uint32_t* AsBuf[2];
    uint32_t* BtBuf[2];
    float*    BfBuf[2];
    AsBuf[0] = (uint32_t*)smem_raw;                 // 128 x AS_STR
    AsBuf[1] = AsBuf[0] + 128*AS_STR;
    BtBuf[0] = AsBuf[1] + 128*AS_STR;               // 16 x BT_STR
    BtBuf[1] = BtBuf[0] + 16*BT_STR;
    BfBuf[0] = (float*)(BtBuf[1] + 16*BT_STR);      // 16 x BF_STR
    BfBuf[1] = BfBuf[0] + 16*BF_STR;
    float* wos = BfBuf[1] + 16*BF_STR;              // [HH]
    float* red = wos + HH;                           // [128][4]

    const int tid  = threadIdx.x;
    const int lane = tid & 31;
    const int warp = tid >> 5;
    const int base = blockIdx.x * 128;

    if (tid < HH) wos[tid] = Wo[tid];

    // staging indices (all threads)
    const int arow = tid >> 2;             // 0..127
    const int acol = (tid & 3) * 4;        // 0,4,8,12
    const int bh   = tid >> 1;             // 0..255 (h); warps 0..11 -> bh<192
    const int bko  = (tid & 1) * 8;        // 0 or 8

    float acc[64];                          // tensor: [mt*32+nt*4+c]; FFMA: [i*8+j]
    #pragma unroll
    for (int i = 0; i < 64; i++) acc[i] = 0.f;

    const float* apt = kmat + (size_t)(base + arow)*KK + acol;
    const float* bpt = Wk + (size_t)bh*KK + bko;

    // ---- staging store helper (done twice: prologue + loop) ----
    #define STAGE_STORE(As, Bt, Bf, av, bv0, bv1) do {                          \
        uint4 at_;                                                              \
        at_.x = f2tf32((av).x); at_.y = f2tf32((av).y);                         \
        at_.z = f2tf32((av).z); at_.w = f2tf32((av).w);                         \
        *(uint4*)&(As)[arow*AS_STR + acol] = at_;                               \
        if (bh < 192) {                                                         \
            (Bt)[(bko+0)*BT_STR + bh] = f2tf32((bv0).x);                        \
            (Bt)[(bko+1)*BT_STR + bh] = f2tf32((bv0).y);                        \
            (Bt)[(bko+2)*BT_STR + bh] = f2tf32((bv0).z);                        \
            (Bt)[(bko+3)*BT_STR + bh] = f2tf32((bv0).w);                        \
            (Bt)[(bko+4)*BT_STR + bh] = f2tf32((bv1).x);                        \
            (Bt)[(bko+5)*BT_STR + bh] = f2tf32((bv1).y);                        \
            (Bt)[(bko+6)*BT_STR + bh] = f2tf32((bv1).z);                        \
            (Bt)[(bko+7)*BT_STR + bh] = f2tf32((bv1).w);                        \
        } else {                                                                \
            int c_ = bh - 192;                                                  \
            (Bf)[(bko+0)*BF_STR + c_] = (bv0).x;                                \
            (Bf)[(bko+1)*BF_STR + c_] = (bv0).y;                                \
            (Bf)[(bko+2)*BF_STR + c_] = (bv0).z;                                \
            (Bf)[(bko+3)*BF_STR + c_] = (bv0).w;                                \
            (Bf)[(bko+4)*BF_STR + c_] = (bv1).x;                                \
            (Bf)[(bko+5)*BF_STR + c_] = (bv1).y;                                \
            (Bf)[(bko+6)*BF_STR + c_] = (bv1).z;                                \
            (Bf)[(bko+7)*BF_STR + c_] = (bv1).w;                                \
        }                                                                       \
    } while (0)

    // ---- prologue: tile 0 -> regs -> smem buf 0 ----
    float4 av  = *(const float4*)(apt);
    float4 bv0 = *(const float4*)(bpt);
    float4 bv1 = *(const float4*)(bpt + 4);
    STAGE_STORE(AsBuf[0], BtBuf[0], BfBuf[0], av, bv0, bv1);
    __syncthreads();

    // role constants
    const int wm = warp & 3;               // tensor: M group
    const int wn = warp >> 2;              // tensor: N group 0..2 (if warp<12)
    const int g  = lane >> 2;
    const int t  = lane & 3;
    const int fw = warp - 12;              // FFMA warp 0..3
    const int ly = lane >> 3;              // FFMA row lane 0..3
    const int lx = lane & 7;               // FFMA col lane 0..7

    for (int it = 0; it < NK_TILES; it++) {
        if (it + 1 < NK_TILES) {
            int kn = (it + 1) * 16;
            av  = *(const float4*)(apt + kn);
            bv0 = *(const float4*)(bpt + kn);
            bv1 = *(const float4*)(bpt + kn + 4);
        }

        const uint32_t* As = AsBuf[it & 1];
        if (warp < 12) {
            // ---- tensor path: 32 x m16n8k8 tf32 MMAs ----
            const uint32_t* Bs = BtBuf[it & 1];
            #pragma unroll
            for (int ks = 0; ks < 2; ks++) {
                const int kk = ks * 8;
                uint32_t afr[2][4];
                #pragma unroll
                for (int mt = 0; mt < 2; mt++) {
                    int r = wm*32 + mt*16;
                    afr[mt][0] = As[(r + g    )*AS_STR + kk + t    ];
                    afr[mt][1] = As[(r + g + 8)*AS_STR + kk + t    ];
                    afr[mt][2] = As[(r + g    )*AS_STR + kk + t + 4];
                    afr[mt][3] = As[(r + g + 8)*AS_STR + kk + t + 4];
                }
                uint32_t bfr[8][2];
                #pragma unroll
                for (int nt = 0; nt < 8; nt++) {
                    int n = wn*64 + nt*8 + g;
                    bfr[nt][0] = Bs[(kk + t    )*BT_STR + n];
                    bfr[nt][1] = Bs[(kk + t + 4)*BT_STR + n];
                }
                #pragma unroll
                for (int mt = 0; mt < 2; mt++)
                    #pragma unroll
                    for (int nt = 0; nt < 8; nt++)
                        MMA_TF32(&acc[mt*32 + nt*4], afr[mt], bfr[nt]);
            }
        } else {
            // ---- FFMA path: rows fw*32 + ly + 4i, cols 192 + lx + 8j ----
            const float* Bf = BfBuf[it & 1];
            #pragma unroll
            for (int kk = 0; kk < 16; kk++) {
                float a[8], b[8];
                #pragma unroll
                for (int i = 0; i < 8; i++)
                    a[i] = __uint_as_float(As[(fw*32 + ly + 4*i)*AS_STR + kk]);
                #pragma unroll
                for (int j = 0; j < 8; j++)
                    b[j] = Bf[kk*BF_STR + lx + 8*j];
                #pragma unroll
                for (int i = 0; i < 8; i++)
                    #pragma unroll
                    for (int j = 0; j < 8; j++)
                        acc[i*8 + j] += a[i] * b[j];
            }
        }

        if (it + 1 < NK_TILES) {
            STAGE_STORE(AsBuf[(it+1) & 1], BtBuf[(it+1) & 1], BfBuf[(it+1) & 1],
                        av, bv0, bv1);
        }
        __syncthreads();
    }

    // ---- epilogue: tanh + Wo-weighted reduce across H ----
    float bo0 = bo[0];
    if (warp < 12) {
        // C mapping: c0 -> (row g, col 2t), c1 -> (g, 2t+1), c2/c3 -> row g+8
        #pragma unroll
        for (int mt = 0; mt < 2; mt++) {
            #pragma unroll
            for (int rr = 0; rr < 2; rr++) {
                int row_local = wm*32 + mt*16 + rr*8 + g;
                int b = (base + row_local) & (BB - 1);
                const float* hqb = g_hq2 + b*HH;
                float part = 0.f;
                #pragma unroll
                for (int nt = 0; nt < 8; nt++) {
                    int h0 = wn*64 + nt*8 + t*2;
                    float x0 = acc[mt*32 + nt*4 + rr*2+0] + __ldg(hqb + h0);
                    float x1 = acc[mt*32 + nt*4 + rr*2+1] + __ldg(hqb + h0 + 1);
                    part += wos[h0] * tanhf(x0) + wos[h0+1] * tanhf(x1);
                }
                part += __shfl_xor_sync(0xffffffffu, part, 1);
                part += __shfl_xor_sync(0xffffffffu, part, 2);
                if (t == 0) red[row_local*4 + wn] = part;
            }
        }
    } else {
        #pragma unroll
        for (int i = 0; i < 8; i++) {
            int row_local = fw*32 + ly + 4*i;
            int b = (base + row_local) & (BB - 1);
            const float* hqb = g_hq2 + b*HH;
            float part = 0.f;
            #pragma unroll
            for (int j = 0; j < 8; j++) {
                int h = 192 + lx + 8*j;
                part += wos[h] * tanhf(acc[i*8 + j] + __ldg(hqb + h));
            }
            part += __shfl_xor_sync(0xffffffffu, part, 1);
            part += __shfl_xor_sync(0xffffffffu, part, 2);
            part += __shfl_xor_sync(0xffffffffu, part, 4);
            if (lx == 0) red[row_local*4 + 3] = part;
        }
    }
    __syncthreads();
    if (tid < 128)
        g_logit[base + tid] = red[tid*4+0] + red[tid*4+1] + red[tid*4+2] + red[tid*4+3] + bo0;
}

// ---------------------------------------------------------------------------
// Kernel 3: softmax per batch over S; writes final p[b*S+s] into the output.
// ---------------------------------------------------------------------------
__global__ void softmax_kernel(float* __restrict__ p) {
    int b = blockIdx.x, t = threadIdx.x;   // 256 threads
    __shared__ float red[256];
    float m = -3.4e38f;
    for (int s = t; s < SS; s += 256) m = fmaxf(m, g_logit[s*BB + b]);
    red[t] = m; __syncthreads();
    for (int off = 128; off; off >>= 1) {
        if (t < off) red[t] = fmaxf(red[t], red[t + off]);
        __syncthreads();
    }
    m = red[0]; __syncthreads();

    float sum = 0.f;
    for (int s = t; s < SS; s += 256) {
        float e = expf(g_logit[s*BB + b] - m);
        p[b*SS + s] = e;
        sum += e;
    }
    red[t] = sum; __syncthreads();
    for (int off = 128; off; off >>= 1) {
        if (t < off) red[t] += red[t + off];
        __syncthreads();
    }
    float rinv = 1.f / red[0];
    for (int s = t; s < SS; s += 256) p[b*SS + s] *= rinv;
}

// ---------------------------------------------------------------------------
// Kernel 4: partial weighted sum over an s-chunk (float4, smem-staged p):
//   g_partial[sc][b][vc] = sum_{s in chunk} p[b][s] * v[s][b][vc]
// ---------------------------------------------------------------------------
__global__ void wsum_kernel(const float* __restrict__ v, const float* __restrict__ p) {
    int b  = blockIdx.x;
    int sc = blockIdx.y;
    int vc4 = threadIdx.x;   // 128 threads, one float4 each (covers V=512)
    __shared__ float ps[SPER];
    if (threadIdx.x < SPER) ps[threadIdx.x] = p[b*SS + sc*SPER + threadIdx.x];
    __syncthreads();

    const float4* vp = (const float4*)(v + ((size_t)(sc*SPER)*BB + b) * VV) + vc4;
    const size_t stride4 = (size_t)BB * VV / 4;  // float4 stride over s
    float4 acc = make_float4(0.f, 0.f, 0.f, 0.f);
    #pragma unroll 8
    for (int s = 0; s < SPER; s++) {
        float  w = ps[s];
        float4 tv = vp[(size_t)s * stride4];
        acc.x += w * tv.x; acc.y += w * tv.y;
        acc.z += w * tv.z; acc.w += w * tv.w;
    }
    ((float4*)(g_partial + ((size_t)(sc*BB + b)) * VV))[vc4] = acc;
}

// ---------------------------------------------------------------------------
// Kernel 5: reduce split-S partials -> out[b*V + vc]  (deterministic)
// ---------------------------------------------------------------------------
__global__ void reduce_kernel(float* __restrict__ out) {
    int idx = blockIdx.x * 256 + threadIdx.x;  // 16384 total
    float acc = 0.f;
    #pragma unroll
    for (int c = 0; c < SCH; c++) acc += g_partial[c*BB*VV + idx];
    out[idx] = acc;
}

// ---------------------------------------------------------------------------
extern "C" void kernel_launch(void* const* d_in, const int* in_sizes, int n_in,
                              void* d_out, int out_size) {
    const float* q  = (const float*)d_in[0];
    const float* k  = (const float*)d_in[1];
    const float* v  = (const float*)d_in[2];
    const float* Wk = (const float*)d_in[3];
    const float* bk = (const float*)d_in[4];
    const float* Wq = (const float*)d_in[5];
    const float* bq = (const float*)d_in[6];
    const float* Wo = (const float*)d_in[7];
    const float* bo = (const float*)d_in[8];

    float* out = (float*)d_out;          // [1, B, V] -> B*V floats
    float* p   = out + BB*VV;            // [B, S]    -> B*S floats

    static int smem_set = 0;
    if (!smem_set) {
        cudaFuncSetAttribute(logit_kernel,
                             cudaFuncAttributeMaxDynamicSharedMemorySize, LOGIT_SMEM);
        smem_set = 1;
    }

    dim3 g1(BB, 8);
    hq_kernel<<<g1, 256>>>(q, Wq, bq, bk);
    logit_kernel<<<MT/128, 512, LOGIT_SMEM>>>(k, Wk, Wo, bo);
    softmax_kernel<<<BB, 256>>>(p);
    dim3 g4(BB, SCH);
    wsum_kernel<<<g4, 128>>>(v, p);
    reduce_kernel<<<BB*VV/256, 256>>>(out);
}